// round 7
// baseline (speedup 1.0000x reference)
#include <cuda_runtime.h>
#include <math.h>
#include <stdint.h>

#define BB   32
#define LL   1024
#define CH   34
#define DD   256
#define EE   8
#define PP   4
#define PRED 96
#define NBLK 128      // <= 148 SMs: all blocks wave-1 resident -> grid barrier safe
#define NTHR 512

typedef unsigned long long ull;
#define FMA2(d, a, b, c) \
    asm("fma.rn.f32x2 %0, %1, %2, %3;" : "=l"(d) : "l"(a), "l"(b), "l"(c))
__device__ __forceinline__ float f2lo(ull v) { return __uint_as_float((unsigned)v); }
__device__ __forceinline__ float f2hi(ull v) { return __uint_as_float((unsigned)(v >> 32)); }

// shared memory layout (float offsets)
#define WPT   0            // 17 x 256 : W_proj^T (row 16 = b_proj)
#define WES   4352         // 16 x 260 : expert W slice
#define RED   8512         // 32 : stats reduce
#define RFOLD 8544         // 68 : router fold partials
#define SXRAW 8612         // 64 : raw channel-2 samples (post)
#define STAT  8676         // 4  : mu, sd, rsd
#define SLOG  8680         // 32 : logits
#define SG    8712         // 32 : gates
#define SF    8744         // 1024 : flat row
#define SM_FLOATS 9768

__device__ float g_M[EE * 17 * DD];   // M_e[k][h]; k=16 row = b_proj.We^T
__device__ float g_R[17 * EE];        // R[k][e];   k=16 row = b_proj.Wr^T + br
__device__ float g_s1[NBLK];
__device__ float g_s2[NBLK];
__device__ unsigned g_barcnt[1];
__device__ float g_dummy[4];

__device__ __forceinline__ void cp16(void* dst_smem, const void* src_gmem) {
    uint32_t d = (uint32_t)__cvta_generic_to_shared(dst_smem);
    asm volatile("cp.async.cg.shared.global [%0], [%1], 16;" :: "r"(d), "l"(src_gmem));
}
__device__ __forceinline__ float ldcg(const float* p) {
    float v; asm volatile("ld.global.cg.f32 %0, [%1];" : "=f"(v) : "l"(p)); return v;
}

// Monotonic release/acquire grid barrier (no gpu-scope membar -> no L1 flush).
__device__ __forceinline__ void grid_barrier() {
    __syncthreads();
    if (threadIdx.x == 0) {
        unsigned old;
        asm volatile("atom.release.gpu.global.add.u32 %0, [%1], 1;"
                     : "=r"(old) : "l"(&g_barcnt[0]) : "memory");
        unsigned target = old - (old % NBLK) + NBLK;
        unsigned cur;
        do {
            __nanosleep(64);
            asm volatile("ld.acquire.gpu.global.u32 %0, [%1];"
                         : "=r"(cur) : "l"(&g_barcnt[0]) : "memory");
        } while (cur < target);
    }
    __syncthreads();
}

__global__ void __launch_bounds__(NTHR, 1)
fused_kernel(const float* __restrict__ x,
             const float* __restrict__ W_proj,
             const float* __restrict__ b_proj,
             const float* __restrict__ W_router,
             const float* __restrict__ b_router,
             const float* __restrict__ W_experts,
             const float* __restrict__ b_experts,
             const float* __restrict__ W_head,
             const float* __restrict__ b_head,
             float* __restrict__ out) {
    __shared__ float sm[SM_FLOATS];
    const int bid = blockIdx.x;
    const int tid = threadIdx.x;

    const int e2 = bid >> 4;           // expert
    const int ct = bid & 15;           // 16-col tile of M_e

    // ---- (1) stage We slice (16 x 256) via cp.async
    {
        const float* Wb = W_experts + ((size_t)e2 * DD + ct * 16) * DD;
#pragma unroll
        for (int i = 0; i < 2; i++) {
            int q = tid + NTHR * i;
            int row = q >> 6, c4 = q & 63;
            cp16(sm + WES + row * 260 + c4 * 4, Wb + row * DD + c4 * 4);
        }
        asm volatile("cp.async.commit_group;");
    }

    // ---- (2) W_proj^T into smem (row 16 = b_proj)
    {
#pragma unroll
        for (int i = 0; i < 2; i++) {
            int idx = tid + NTHR * i;
            int d = idx >> 2, kq = idx & 3;
            float4 v = __ldg((const float4*)W_proj + idx);
            sm[WPT + (kq * 4 + 0) * 256 + d] = v.x;
            sm[WPT + (kq * 4 + 1) * 256 + d] = v.y;
            sm[WPT + (kq * 4 + 2) * 256 + d] = v.z;
            sm[WPT + (kq * 4 + 3) * 256 + d] = v.w;
        }
        if (tid < 256) sm[WPT + 16 * 256 + tid] = __ldg(b_proj + tid);
    }

    // ---- (3) stats partials + L2 prefetch of post-phase weights
    {
        int b = bid >> 2, seg = bid & 3;
        const float* xrow = x + (size_t)b * (LL * CH);
        int base = seg * 8704;
        float s1 = 0.f, s2 = 0.f;
#pragma unroll
        for (int i = 0; i < 5; i++) {
            int v4 = tid + NTHR * i;
            if (v4 < 2176) {
                float4 q = __ldg((const float4*)(xrow + base) + v4);
                int w0 = base + v4 * 4;
                int m = w0 % 34;
                int jm = 2 - m; if (jm < 0) jm += 34;
                if (jm < 4) {
                    float val = (jm == 0) ? q.x : (jm == 1) ? q.y : (jm == 2) ? q.z : q.w;
                    s1 += val; s2 += val * val;
                }
            }
        }

        float pf = 0.f;
        if (tid < 192) {                           // W_head fully covered -> L2
            float4 wq = __ldg((const float4*)W_head + bid * 192 + tid);
            pf += wq.x + wq.y + wq.z + wq.w;
        }
        if (bid == 1) {                            // b_experts (512 float4)
            float4 bq = __ldg((const float4*)b_experts + tid);
            pf += bq.x + bq.y + bq.z + bq.w;
        } else if (bid == 2) {                     // W_router (512 float4)
            float4 rq = __ldg((const float4*)W_router + tid);
            pf += rq.x + rq.y + rq.z + rq.w;
        } else if (bid == 3) {
            if (tid < PRED) pf += __ldg(b_head + tid);
            if (tid < EE)   pf += __ldg(b_router + tid);
        }
        if (pf == 1.2345e-30f) g_dummy[0] = pf;

#pragma unroll
        for (int off = 16; off > 0; off >>= 1) {
            s1 += __shfl_xor_sync(0xffffffffu, s1, off);
            s2 += __shfl_xor_sync(0xffffffffu, s2, off);
        }
        if ((tid & 31) == 0) { sm[RED + (tid >> 5)] = s1; sm[RED + 16 + (tid >> 5)] = s2; }
    }

    asm volatile("cp.async.wait_group 0;" ::: "memory");
    __syncthreads();

    if (tid == 0) {
        float a = 0.f, c = 0.f;
#pragma unroll
        for (int w = 0; w < 16; w++) { a += sm[RED + w]; c += sm[RED + 16 + w]; }
        g_s1[bid] = a;
        g_s2[bid] = c;
    }

    // ---- (4) M_e tile: M[k][c] = wp_t[k] . We_s[c]   (272 threads, f32x2)
    if (tid < 272) {
        int k = tid >> 4, c = tid & 15;
        const ulonglong2* wp2 = (const ulonglong2*)(sm + WPT + k * 256);
        const ulonglong2* we2 = (const ulonglong2*)(sm + WES + c * 260);
        ull acc = 0ull;
#pragma unroll 8
        for (int i = 0; i < 64; i++) {
            ulonglong2 wv = wp2[i], ev = we2[i];
            FMA2(acc, wv.x, ev.x, acc);
            FMA2(acc, wv.y, ev.y, acc);
        }
        g_M[(e2 * 17 + k) * DD + ct * 16 + c] = f2lo(acc) + f2hi(acc);
    }

    // ---- (5) router fold partials (ct==0): 68 threads, k x 4 lanes x 16 float4
    if (ct == 0 && tid >= 272 && tid < 340) {
        int t = tid - 272;
        int k = t >> 2, q = t & 3;
        const float4* wr4 = (const float4*)(W_router + e2 * DD) + q * 16;
        const float4* wp4 = (const float4*)(sm + WPT + k * 256) + q * 16;
        float a0 = 0.f, a1 = 0.f;
#pragma unroll
        for (int i = 0; i < 16; i++) {
            float4 w = __ldg(wr4 + i), p = wp4[i];
            a0 += w.x * p.x + w.y * p.y;
            a1 += w.z * p.z + w.w * p.w;
        }
        sm[RFOLD + t] = a0 + a1;
    }
    __syncthreads();
    if (ct == 0 && tid < 17) {
        float acc = sm[RFOLD + tid * 4] + sm[RFOLD + tid * 4 + 1]
                  + sm[RFOLD + tid * 4 + 2] + sm[RFOLD + tid * 4 + 3];
        if (tid == 16) acc += __ldg(b_router + e2);
        g_R[tid * EE + e2] = acc;
    }

    grid_barrier();

    // ================= Post: gates (warp0) || expert dots (all) ==============
    {
        int b = bid >> 2, jt = bid & 3;

        float rawv = 0.f;
        if (tid < 64) rawv = __ldg(x + ((size_t)b * LL + tid) * CH + 2);
        if (tid == 64) {
            float s1 = 0.f, s2 = 0.f;
#pragma unroll
            for (int s = 0; s < 4; s++) { s1 += ldcg(g_s1 + b * 4 + s); s2 += ldcg(g_s2 + b * 4 + s); }
            float mu = s1 * (1.0f / 1024.0f);
            float var = s2 * (1.0f / 1024.0f) - mu * mu;
            float sd = sqrtf(var + 1e-5f);
            sm[STAT] = mu; sm[STAT + 1] = sd; sm[STAT + 2] = 1.0f / sd;
        }
        if (tid < 64) sm[SXRAW + tid] = rawv;
        __syncthreads();

        float mu = sm[STAT], sd = sm[STAT + 1], rsd = sm[STAT + 2];

        // gates: warp 0 only (runs concurrently with other warps' dot products)
        if (tid < 32) {
            int p = tid >> 3, e = tid & 7;
            float acc = ldcg(g_R + 16 * EE + e);
            const float* xr = sm + SXRAW + p * 16;
#pragma unroll
            for (int k = 0; k < 16; k++)
                acc += ((xr[k] - mu) * rsd) * ldcg(g_R + k * EE + e);
            sm[SLOG + tid] = acc;
            __syncwarp();
            if (tid < PP) {
                int pp = tid;
                float m = -1e30f;
#pragma unroll
                for (int e3 = 0; e3 < EE; e3++) m = fmaxf(m, sm[SLOG + pp * 8 + e3]);
                float ex[EE], sum = 0.f;
#pragma unroll
                for (int e3 = 0; e3 < EE; e3++) { ex[e3] = __expf(sm[SLOG + pp * 8 + e3] - m); sum += ex[e3]; }
                float inv = 1.0f / sum;
#pragma unroll
                for (int e3 = 0; e3 < EE; e3++) sm[SG + pp * 8 + e3] = ex[e3] * inv;
            }
        }

        // heavy: per-expert dots, all 512 threads, 2 patches each (gate-independent)
        int h = tid & 255, pg = tid >> 8;
        float xh0[16], xh1[16];
#pragma unroll
        for (int k = 0; k < 16; k++) {
            xh0[k] = (sm[SXRAW + (pg * 2) * 16 + k] - mu) * rsd;
            xh1[k] = (sm[SXRAW + (pg * 2 + 1) * 16 + k] - mu) * rsd;
        }
        float s0[EE], s1v[EE];
#pragma unroll
        for (int e = 0; e < EE; e++) {
            float m[17];
#pragma unroll
            for (int k = 0; k < 17; k++) m[k] = ldcg(g_M + (e * 17 + k) * DD + h);
            float cb = m[16] + __ldg(b_experts + e * DD + h);
            float t0 = cb, t1 = cb;
#pragma unroll
            for (int k = 0; k < 16; k++) { t0 += xh0[k] * m[k]; t1 += xh1[k] * m[k]; }
            s0[e] = t0; s1v[e] = t1;
        }
        __syncthreads();   // gates (warp 0) now visible

        float a0 = 0.f, a1 = 0.f;
#pragma unroll
        for (int e = 0; e < EE; e++) {
            a0 += sm[SG + (pg * 2) * 8 + e] * s0[e];
            a1 += sm[SG + (pg * 2 + 1) * 8 + e] * s1v[e];
        }
        sm[SF + (pg * 2) * 256 + h]     = a0 * sd + mu;
        sm[SF + (pg * 2 + 1) * 256 + h] = a1 * sd + mu;
        __syncthreads();

        // head GEMV: 24 rows x 16 lanes (W_head L2-hot)
        if (tid < 384) {
            int row = tid >> 4, s = tid & 15;
            int j = jt * 24 + row;
            const float4* wr = (const float4*)(W_head + (size_t)j * LL) + s * 16;
            const float4* sv = (const float4*)(sm + SF) + s * 16;
            float a = 0.f;
#pragma unroll
            for (int i = 0; i < 16; i++) {
                float4 wv = __ldg(wr + i);
                float4 xv = sv[i];
                a += wv.x * xv.x + wv.y * xv.y + wv.z * xv.z + wv.w * xv.w;
            }
#pragma unroll
            for (int off = 8; off > 0; off >>= 1)
                a += __shfl_down_sync(0xffffffffu, a, off, 16);
            if (s == 0) out[b * PRED + j] = a + __ldg(b_head + j);
        }
    }
}

extern "C" void kernel_launch(void* const* d_in, const int* in_sizes, int n_in,
                              void* d_out, int out_size) {
    const float* x         = (const float*)d_in[0];
    const float* W_proj    = (const float*)d_in[4];
    const float* b_proj    = (const float*)d_in[5];
    const float* W_router  = (const float*)d_in[6];
    const float* b_router  = (const float*)d_in[7];
    const float* W_experts = (const float*)d_in[8];
    const float* b_experts = (const float*)d_in[9];
    const float* W_head    = (const float*)d_in[10];
    const float* b_head    = (const float*)d_in[11];
    float* out = (float*)d_out;

    fused_kernel<<<NBLK, NTHR>>>(x, W_proj, b_proj, W_router, b_router,
                                 W_experts, b_experts, W_head, b_head, out);
}